// round 13
// baseline (speedup 1.0000x reference)
#include <cuda_runtime.h>
#include <math.h>
#include <stdint.h>

#define NB 4096
#define LL 200
#define DD 128
#define HH 100
#define NTHREADS 512
#define MBLOCKS 13
#define NPAIRS 7
#define NPAD 112
#define XSTRIDE 132
#define NCHUNK 8                 // K chunks of 16 cols

// ---- smem layout (float indices) ----
#define XS_F 0                            // x [208][132]            = 27456
#define BQ_F (XS_F + 208 * XSTRIDE)       // B quads 3584 float4     = 14336
#define TB_F (BQ_F + 14336)               // temp Wk flat            = 12800
#define QV_F (TB_F + 12800)               // bk + qWq [112]
#define VV_F (QV_F + NPAD)                // v [112]
#define SS_F (VV_F + NPAD)                // a[l] [208]
#define MK_F (SS_F + 208)                 // mask [208]
#define RD_F (MK_F + 208)                 // quarter partials [512]
#define DN_F (RD_F + 512)                 // denom
#define SMEM_FLOATS (DN_F + 8)
#define SMEM_BYTES (SMEM_FLOATS * 4)      // 223040 B

__device__ float g_qv[NB * NPAD];

__device__ __forceinline__ float htanh(float x) {
    float y; asm("tanh.approx.f32 %0, %1;" : "=f"(y) : "f"(x)); return y;
}
__device__ __forceinline__ uint32_t smem_u32(const void* p) {
    uint32_t a;
    asm("{ .reg .u64 t; cvta.to.shared.u64 t, %1; cvt.u32.u64 %0, t; }" : "=r"(a) : "l"(p));
    return a;
}
__device__ __forceinline__ void cp16(uint32_t dst, const void* src) {
    asm volatile("cp.async.ca.shared.global [%0], [%1], 16;" :: "r"(dst), "l"(src));
}
#define CP_COMMIT() asm volatile("cp.async.commit_group;" ::: "memory")
#define CP_WAIT(n)  asm volatile("cp.async.wait_group %0;" :: "n"(n) : "memory")

__device__ __forceinline__ void mma_tf32(float* c, const uint32_t a[4],
                                         uint32_t b0, uint32_t b1) {
    asm volatile(
        "mma.sync.aligned.m16n8k8.row.col.f32.tf32.tf32.f32 "
        "{%0,%1,%2,%3}, {%4,%5,%6,%7}, {%8,%9}, {%0,%1,%2,%3};"
        : "+f"(c[0]), "+f"(c[1]), "+f"(c[2]), "+f"(c[3])
        : "r"(a[0]), "r"(a[1]), "r"(a[2]), "r"(a[3]), "r"(b0), "r"(b1));
}

// ---------- kernel 1: qv[b,h] = bk[h] + q[b,:] @ Wq[:,h] ----------
__global__ void __launch_bounds__(128) qv_kernel(
    const float* __restrict__ q, const float* __restrict__ Wq,
    const float* __restrict__ bk)
{
    __shared__ float qs[DD];
    const int b = blockIdx.x, tid = threadIdx.x;
    qs[tid] = q[(size_t)b * DD + tid];
    __syncthreads();
    if (tid < NPAD) {
        float acc = 0.0f;
        if (tid < HH) {
            acc = bk[tid];
            #pragma unroll 8
            for (int d = 0; d < DD; d++) acc += qs[d] * __ldg(Wq + d * HH + tid);
        }
        g_qv[(size_t)b * NPAD + tid] = acc;
    }
}

// ---------- kernel 2: pipelined fused attention ----------
__global__ void __launch_bounds__(NTHREADS, 1) mxqa_kernel(
    const float* __restrict__ x, const float* __restrict__ Wk,
    const float* __restrict__ v, float* __restrict__ out)
{
    extern __shared__ __align__(16) float sm[];
    float*  xs  = sm + XS_F;
    float4* bq4 = reinterpret_cast<float4*>(sm + BQ_F);
    float*  tb  = sm + TB_F;
    float*  qv  = sm + QV_F;
    float*  vv  = sm + VV_F;
    float*  ss  = sm + SS_F;
    float*  mk  = sm + MK_F;
    float*  rd  = sm + RD_F;

    const int b    = blockIdx.x;
    const int tid  = threadIdx.x;
    const int lane = tid & 31;
    const int wid  = tid >> 5;
    const int g    = lane >> 2;   // row within 8-row group
    const int t    = lane & 3;    // col quad

    const uint32_t sb = smem_u32(sm);
    const float* xg = x + (size_t)b * (LL * DD);

    // ---- issue ALL async copies up front: B (group 0), x chunks (groups 1..8) ----
    #pragma unroll 1
    for (int i = tid; i < (DD * HH) / 4; i += NTHREADS)       // 3200 float4
        cp16(sb + (TB_F + 4 * i) * 4, Wk + 4 * i);
    CP_COMMIT();
    #pragma unroll 1
    for (int c = 0; c < NCHUNK; c++) {
        #pragma unroll 1
        for (int i = tid; i < LL * 4; i += NTHREADS) {        // 800 float4 per chunk
            const int l = i >> 2, j = i & 3;
            cp16(sb + (XS_F + l * XSTRIDE + c * 16 + j * 4) * 4,
                 xg + l * DD + c * 16 + j * 4);
        }
        CP_COMMIT();
    }

    // ---- small-array init ----
    if (tid == 0) sm[DN_F] = 0.0f;
    if (tid < NPAD) {
        qv[tid] = g_qv[(size_t)b * NPAD + tid];
        vv[tid] = (tid < HH) ? v[tid] : 0.0f;
    }
    if (tid < 208) mk[tid] = 0.0f;

    // ---- wait for B, build fragment-quad layout bq ----
    CP_WAIT(8);
    __syncthreads();
    #pragma unroll 1
    for (int qd = tid; qd < 16 * NPAIRS * 32; qd += NTHREADS) {   // 3584 quads
        const int gg = qd & 7, tt = (qd >> 3) & 3;
        const int rest = qd >> 5;
        const int np = rest % NPAIRS, ks = rest / NPAIRS;
        const int k = ks * 8 + tt, n = np * 16 + gg;
        float4 o;
        o.x = (n < HH)     ? tb[k * HH + n]           : 0.0f;
        o.y = (n < HH)     ? tb[(k + 4) * HH + n]     : 0.0f;
        o.z = (n + 8 < HH) ? tb[k * HH + n + 8]       : 0.0f;
        o.w = (n + 8 < HH) ? tb[(k + 4) * HH + n + 8] : 0.0f;
        bq4[qd] = o;
    }

    // ---- pipelined GEMM over 8 K-chunks ----
    float cc[NPAIRS][8];
    #pragma unroll
    for (int np = 0; np < NPAIRS; np++)
        #pragma unroll
        for (int j = 0; j < 8; j++) cc[np][j] = 0.0f;

    const float* xr = xs + (wid * 16 + g) * XSTRIDE + t;

#define CHUNK_BODY(C, WG)                                                       \
    do {                                                                        \
        CP_WAIT(WG);                                                            \
        __syncthreads();                                                        \
        for (int i = tid; i < LL * 4; i += NTHREADS) {                          \
            const int l = i >> 2, j = i & 3;                                    \
            float4 xv = *reinterpret_cast<const float4*>(                       \
                xs + l * XSTRIDE + (C) * 16 + j * 4);                           \
            if (xv.x != 0.f || xv.y != 0.f || xv.z != 0.f || xv.w != 0.f)       \
                mk[l] = 1.0f;                                                   \
        }                                                                       \
        if (wid < MBLOCKS) {                                                    \
            _Pragma("unroll")                                                   \
            for (int ksl = 0; ksl < 2; ksl++) {                                 \
                uint32_t a[4];                                                  \
                a[0] = __float_as_uint(xr[(C) * 16 + ksl * 8]);                 \
                a[1] = __float_as_uint(xr[(C) * 16 + ksl * 8 + 8 * XSTRIDE]);   \
                a[2] = __float_as_uint(xr[(C) * 16 + ksl * 8 + 4]);             \
                a[3] = __float_as_uint(xr[(C) * 16 + ksl * 8 + 8 * XSTRIDE + 4]);\
                const float4* bp = bq4 + ((C) * 2 + ksl) * NPAIRS * 32          \
                                 + t * 8 + g;                                   \
                _Pragma("unroll")                                               \
                for (int np = 0; np < NPAIRS; np++) {                           \
                    float4 bv = bp[np * 32];                                    \
                    mma_tf32(cc[np],     a, __float_as_uint(bv.x),              \
                                            __float_as_uint(bv.y));             \
                    mma_tf32(cc[np] + 4, a, __float_as_uint(bv.z),              \
                                            __float_as_uint(bv.w));             \
                }                                                               \
            }                                                                   \
        }                                                                       \
    } while (0)

    CHUNK_BODY(0, 7); CHUNK_BODY(1, 6); CHUNK_BODY(2, 5); CHUNK_BODY(3, 4);
    CHUNK_BODY(4, 3); CHUNK_BODY(5, 2); CHUNK_BODY(6, 1); CHUNK_BODY(7, 0);
#undef CHUNK_BODY

    // ---- fused epilogue: tanh + v-dot, exp * mask ----
    if (wid < MBLOCKS) {
        float sc_lo = 0.0f, sc_hi = 0.0f;
        #pragma unroll
        for (int np = 0; np < NPAIRS; np++) {
            const int h0 = np * 16 + 2 * t;
            sc_lo += vv[h0]     * htanh(cc[np][0] + qv[h0])
                   + vv[h0 + 1] * htanh(cc[np][1] + qv[h0 + 1]);
            sc_hi += vv[h0]     * htanh(cc[np][2] + qv[h0])
                   + vv[h0 + 1] * htanh(cc[np][3] + qv[h0 + 1]);
            sc_lo += vv[h0 + 8] * htanh(cc[np][4] + qv[h0 + 8])
                   + vv[h0 + 9] * htanh(cc[np][5] + qv[h0 + 9]);
            sc_hi += vv[h0 + 8] * htanh(cc[np][6] + qv[h0 + 8])
                   + vv[h0 + 9] * htanh(cc[np][7] + qv[h0 + 9]);
        }
        sc_lo += __shfl_xor_sync(0xffffffffu, sc_lo, 1);
        sc_lo += __shfl_xor_sync(0xffffffffu, sc_lo, 2);
        sc_hi += __shfl_xor_sync(0xffffffffu, sc_hi, 1);
        sc_hi += __shfl_xor_sync(0xffffffffu, sc_hi, 2);
        if (t == 0) {
            const int r = wid * 16 + g;
            if (r < LL)     ss[r]     = __expf(sc_lo) * mk[r];
            if (r + 8 < LL) ss[r + 8] = __expf(sc_hi) * mk[r + 8];
        }
    }
    __syncthreads();

    // ---- denominator ----
    {
        float av = (tid < LL) ? ss[tid] : 0.0f;
        #pragma unroll
        for (int o = 16; o > 0; o >>= 1) av += __shfl_down_sync(0xffffffffu, av, o);
        if (lane == 0 && wid < 7) atomicAdd(&sm[DN_F], av);
    }
    __syncthreads();
    const float inv = 1.0f / (sm[DN_F] + 1e-7f);

    // ---- out[b,d] = inv * sum_l x[l,d]*a[l]  (four l-quarters) ----
    {
        const int d = tid & 127, quarter = tid >> 7;
        const int l0 = quarter * 50;
        float acc = 0.0f;
        #pragma unroll 5
        for (int l = l0; l < l0 + 50; l++)
            acc += xs[l * XSTRIDE + d] * ss[l];
        rd[quarter * DD + d] = acc;
        __syncthreads();
        if (quarter == 0)
            out[(size_t)b * DD + d] =
                (rd[d] + rd[DD + d] + rd[2 * DD + d] + rd[3 * DD + d]) * inv;
    }
}

extern "C" void kernel_launch(void* const* d_in, const int* in_sizes, int n_in,
                              void* d_out, int out_size)
{
    const float* x  = (const float*)d_in[0];
    const float* q  = (const float*)d_in[1];
    const float* Wk = (const float*)d_in[2];
    const float* bk = (const float*)d_in[3];
    const float* Wq = (const float*)d_in[4];
    const float* v  = (const float*)d_in[5];
    float* out = (float*)d_out;

    cudaFuncSetAttribute(mxqa_kernel, cudaFuncAttributeMaxDynamicSharedMemorySize,
                         SMEM_BYTES);
    qv_kernel<<<NB, 128>>>(q, Wq, bk);
    mxqa_kernel<<<NB, NTHREADS, SMEM_BYTES>>>(x, Wk, v, out);
}

// round 14
// speedup vs baseline: 1.3839x; 1.3839x over previous
#include <cuda_runtime.h>
#include <math.h>
#include <stdint.h>

#define NB 4096
#define LL 200
#define DD 128
#define HH 100
#define NTHREADS 512

#define MPAD 208            // 13 * 16
#define NPAD 112            // 14 * 8
#define XSTRIDE 132         // x smem row stride (floats)
#define MBLOCKS 13
#define NPAIRS 7
#define KSTEPS 16           // 128 / 8

// ---- smem layout (float indices) ----
#define XS_F 0                            // x  [208][132] = 27456
#define BQ_F (XS_F + MPAD * XSTRIDE)      // B quads: 16*7*32 float4 = 14336 f
#define QV_F (BQ_F + 16 * NPAIRS * 32 * 4)// bk + qWq [112]
#define VV_F (QV_F + NPAD)                // v [112]
#define SS_F (VV_F + NPAD)                // a[l] [208]
#define MK_F (SS_F + MPAD)                // mask [208]
#define RD_F (MK_F + MPAD)                // quarter partials [4*128]
#define DN_F (RD_F + 4 * DD)              // denom
#define SMEM_FLOATS (DN_F + 4)
#define SMEM_BYTES (SMEM_FLOATS * 4)      // ~172 KB

__device__ float g_qv[NB * NPAD];         // precomputed bk + q@Wq

__device__ __forceinline__ float htanh(float x) {
    float y; asm("tanh.approx.f32 %0, %1;" : "=f"(y) : "f"(x)); return y;
}
__device__ __forceinline__ void mma_tf32(float* c, const uint32_t a[4],
                                         uint32_t b0, uint32_t b1) {
    asm volatile(
        "mma.sync.aligned.m16n8k8.row.col.f32.tf32.tf32.f32 "
        "{%0,%1,%2,%3}, {%4,%5,%6,%7}, {%8,%9}, {%0,%1,%2,%3};"
        : "+f"(c[0]), "+f"(c[1]), "+f"(c[2]), "+f"(c[3])
        : "r"(a[0]), "r"(a[1]), "r"(a[2]), "r"(a[3]), "r"(b0), "r"(b1));
}

// ---------- kernel 1: qv[b,h] = bk[h] + q[b,:] @ Wq[:,h] ----------
__global__ void __launch_bounds__(128) qv_kernel(
    const float* __restrict__ q, const float* __restrict__ Wq,
    const float* __restrict__ bk)
{
    __shared__ float qs[DD];
    const int b = blockIdx.x, tid = threadIdx.x;
    qs[tid] = q[(size_t)b * DD + tid];
    __syncthreads();
    if (tid < NPAD) {
        float acc = 0.0f;
        if (tid < HH) {
            acc = bk[tid];
            #pragma unroll 8
            for (int d = 0; d < DD; d++) acc += qs[d] * __ldg(Wq + d * HH + tid);
        }
        g_qv[(size_t)b * NPAD + tid] = acc;
    }
}

// ---------- kernel 2: main fused attention ----------
__global__ void __launch_bounds__(NTHREADS, 1) mxqa_kernel(
    const float* __restrict__ x, const float* __restrict__ Wk,
    const float* __restrict__ v, float* __restrict__ out)
{
    extern __shared__ __align__(16) float sm[];
    float*  xs  = sm + XS_F;
    float4* bq4 = reinterpret_cast<float4*>(sm + BQ_F);
    float*  qv  = sm + QV_F;
    float*  vv  = sm + VV_F;
    float*  ss  = sm + SS_F;
    float*  mk  = sm + MK_F;
    float*  rd  = sm + RD_F;

    const int b    = blockIdx.x;
    const int tid  = threadIdx.x;
    const int lane = tid & 31;
    const int wid  = tid >> 5;
    const int g    = lane >> 2;   // row within 8-row group
    const int t    = lane & 3;    // col quad

    if (tid == 0) sm[DN_F] = 0.0f;
    if (tid < NPAD) {
        qv[tid] = g_qv[(size_t)b * NPAD + tid];
        vv[tid] = (tid < HH) ? v[tid] : 0.0f;
    }

    // ---- stage x[b] (coalesced float4) + mask via ballot ----
    {
        const float4* xg = reinterpret_cast<const float4*>(x + (size_t)b * (LL * DD));
        #pragma unroll 1
        for (int i = tid; i < LL * (DD / 4); i += NTHREADS) {
            const int l = i >> 5, d4 = i & 31;        // whole warp shares l
            float4 xv = xg[i];
            *reinterpret_cast<float4*>(xs + l * XSTRIDE + d4 * 4) = xv;
            bool nz = (xv.x != 0.f) || (xv.y != 0.f) || (xv.z != 0.f) || (xv.w != 0.f);
            unsigned bal = __ballot_sync(0xffffffffu, nz);
            if (lane == 0) mk[l] = bal ? 1.0f : 0.0f;
        }
    }

    // ---- build B quads directly from global Wk (L2-hot) ----
    // quad index qd = ks*224 + np*32 + (g<<2 | t); holds the 4 B fragment
    // values for lane (g,t) of N-pair np at k-step ks.
    #pragma unroll 1
    for (int qd = tid; qd < KSTEPS * NPAIRS * 32; qd += NTHREADS) {
        const int tt = qd & 3, gg = (qd >> 2) & 7;
        const int rest = qd >> 5;
        const int np = rest % NPAIRS, ks = rest / NPAIRS;
        const int k = ks * 8 + tt, n = np * 16 + gg;
        float4 o;
        o.x = (n < HH)     ? __ldg(Wk + k * HH + n)           : 0.0f;
        o.y = (n < HH)     ? __ldg(Wk + (k + 4) * HH + n)     : 0.0f;
        o.z = (n + 8 < HH) ? __ldg(Wk + k * HH + n + 8)       : 0.0f;
        o.w = (n + 8 < HH) ? __ldg(Wk + (k + 4) * HH + n + 8) : 0.0f;
        bq4[qd] = o;
    }
    __syncthreads();

    // ---- GEMM: ks OUTER / np inner -> 14 independent accumulator chains ----
    float cc[NPAIRS][8];
    #pragma unroll
    for (int np = 0; np < NPAIRS; np++)
        #pragma unroll
        for (int j = 0; j < 8; j++) cc[np][j] = 0.0f;

    if (wid < MBLOCKS) {
        const float* xr = xs + (wid * 16 + g) * XSTRIDE + t;
        const float4* bl = bq4 + lane;
        #pragma unroll
        for (int ks = 0; ks < KSTEPS; ks++) {
            uint32_t a[4];
            a[0] = __float_as_uint(xr[ks * 8]);
            a[1] = __float_as_uint(xr[ks * 8 + 8 * XSTRIDE]);
            a[2] = __float_as_uint(xr[ks * 8 + 4]);
            a[3] = __float_as_uint(xr[ks * 8 + 8 * XSTRIDE + 4]);
            const float4* bp = bl + ks * (NPAIRS * 32);
            #pragma unroll
            for (int np = 0; np < NPAIRS; np++) {
                const float4 bv = bp[np * 32];
                mma_tf32(cc[np],     a, __float_as_uint(bv.x), __float_as_uint(bv.y));
                mma_tf32(cc[np] + 4, a, __float_as_uint(bv.z), __float_as_uint(bv.w));
            }
        }

        // ---- fused epilogue: tanh + v-dot ----
        float sc_lo = 0.0f, sc_hi = 0.0f;
        #pragma unroll
        for (int np = 0; np < NPAIRS; np++) {
            const int h0 = np * 16 + 2 * t;
            sc_lo += vv[h0]     * htanh(cc[np][0] + qv[h0])
                   + vv[h0 + 1] * htanh(cc[np][1] + qv[h0 + 1]);
            sc_hi += vv[h0]     * htanh(cc[np][2] + qv[h0])
                   + vv[h0 + 1] * htanh(cc[np][3] + qv[h0 + 1]);
            sc_lo += vv[h0 + 8] * htanh(cc[np][4] + qv[h0 + 8])
                   + vv[h0 + 9] * htanh(cc[np][5] + qv[h0 + 9]);
            sc_hi += vv[h0 + 8] * htanh(cc[np][6] + qv[h0 + 8])
                   + vv[h0 + 9] * htanh(cc[np][7] + qv[h0 + 9]);
        }
        sc_lo += __shfl_xor_sync(0xffffffffu, sc_lo, 1);
        sc_lo += __shfl_xor_sync(0xffffffffu, sc_lo, 2);
        sc_hi += __shfl_xor_sync(0xffffffffu, sc_hi, 1);
        sc_hi += __shfl_xor_sync(0xffffffffu, sc_hi, 2);
        if (t == 0) {
            const int r = wid * 16 + g;
            if (r < LL)     ss[r]     = __expf(sc_lo) * mk[r];
            if (r + 8 < LL) ss[r + 8] = __expf(sc_hi) * mk[r + 8];
        }
    }
    __syncthreads();

    // ---- denominator ----
    {
        float av = (tid < LL) ? ss[tid] : 0.0f;
        #pragma unroll
        for (int o = 16; o > 0; o >>= 1) av += __shfl_down_sync(0xffffffffu, av, o);
        if (lane == 0 && wid < 7) atomicAdd(&sm[DN_F], av);
    }
    __syncthreads();
    const float inv = 1.0f / (sm[DN_F] + 1e-7f);

    // ---- out[b,d] = inv * sum_l x[l,d]*a[l]  (four l-quarters) ----
    {
        const int d = tid & 127, quarter = tid >> 7;
        const int l0 = quarter * 50;
        float acc = 0.0f;
        #pragma unroll 5
        for (int l = l0; l < l0 + 50; l++)
            acc += xs[l * XSTRIDE + d] * ss[l];
        rd[quarter * DD + d] = acc;
        __syncthreads();
        if (quarter == 0)
            out[(size_t)b * DD + d] =
                (rd[d] + rd[DD + d] + rd[2 * DD + d] + rd[3 * DD + d]) * inv;
    }
}

extern "C" void kernel_launch(void* const* d_in, const int* in_sizes, int n_in,
                              void* d_out, int out_size)
{
    const float* x  = (const float*)d_in[0];
    const float* q  = (const float*)d_in[1];
    const float* Wk = (const float*)d_in[2];
    const float* bk = (const float*)d_in[3];
    const float* Wq = (const float*)d_in[4];
    const float* v  = (const float*)d_in[5];
    float* out = (float*)d_out;

    cudaFuncSetAttribute(mxqa_kernel, cudaFuncAttributeMaxDynamicSharedMemorySize,
                         SMEM_BYTES);
    qv_kernel<<<NB, 128>>>(q, Wq, bk);
    mxqa_kernel<<<NB, NTHREADS, SMEM_BYTES>>>(x, Wk, v, out);
}